// round 14
// baseline (speedup 1.0000x reference)
#include <cuda_runtime.h>
#include <cstdint>

#define BROWS 256
#define DCOLS 131072
#define NCHUNK1 8
#define CH1 16384

// GEMM config (int8): stage = 128 int8 elems = 128B rows
#define KS2  64             // K chunks
#define KCH2 2048           // K elems per chunk (per CTA)
#define KSTG 128            // K elems per stage (128B rows)
#define NSTG (KCH2 / KSTG)  // 16
#define NTILE 10            // 3 HH (2 diag) + 4 HL + 3 LL (2 diag)
#define ABUF2 32768         // bytes per pipeline buffer (2 arrays x 16KB)
#define PSTG 4              // pipeline depth (128 KB smem)

// ---------------- scratch (static device globals; no allocation) ----------------
__device__ float     g_rowsum_part[BROWS * NCHUNK1];
__device__ unsigned  g_bitmap_part[BROWS * NCHUNK1];
__device__ int8_t    g_h8[(size_t)BROWS * DCOLS];         // 33.5 MB
__device__ int8_t    g_l8[(size_t)BROWS * DCOLS];         // 33.5 MB
__device__ int       g_Gpart[(size_t)NTILE * KS2 * 128 * 128]; // 41.9 MB int32
__device__ long long g_GtileI[NTILE * 16384];             // exact per-tile sums
__device__ double    g_Gd[BROWS * BROWS];
__device__ double    g_mu[BROWS], g_istd[BROWS], g_f1[BROWS], g_rowGd[BROWS];
__device__ int       g_ru[BROWS], g_tu;
__device__ float     g_p;
__device__ float     g_scale;

// ---------------- portable PTX helpers (valid at compute_103) ----------------
__device__ __forceinline__ uint32_t smem_u32(const void* p) {
    uint32_t a;
    asm("{ .reg .u64 t; cvta.to.shared.u64 t, %1; cvt.u32.u64 %0, t; }" : "=r"(a) : "l"(p));
    return a;
}
__device__ __forceinline__ uint32_t swz(uint32_t off) { return off ^ ((off >> 3) & 0x70); }

#define CP_ASYNC16(dst, src) \
    asm volatile("cp.async.cg.shared.global [%0], [%1], 16;" :: "r"(dst), "l"(src) : "memory")
#define CP_COMMIT() asm volatile("cp.async.commit_group;" ::: "memory")
#define CP_WAIT(n)  asm volatile("cp.async.wait_group %0;" :: "n"(n) : "memory")

#define LDMX4(R, addr) \
    asm volatile("ldmatrix.sync.aligned.m8n8.x4.shared.b16 {%0,%1,%2,%3}, [%4];" \
        : "=r"((R)[0]), "=r"((R)[1]), "=r"((R)[2]), "=r"((R)[3]) : "r"(addr))

#define MMA_S8(D, A, B0, B1) \
    asm volatile("mma.sync.aligned.m16n8k32.row.col.s32.s8.s8.s32 " \
        "{%0,%1,%2,%3}, {%4,%5,%6,%7}, {%8,%9}, {%0,%1,%2,%3};" \
        : "+r"((D)[0]), "+r"((D)[1]), "+r"((D)[2]), "+r"((D)[3]) \
        : "r"((A)[0]), "r"((A)[1]), "r"((A)[2]), "r"((A)[3]), "r"(B0), "r"(B1))

// ---- dummy: shims so k2 lands at the ncu capture slot (launch index 3) ----
__global__ void kdummy() {}

// ---- K1: row sums + 32-bin bitmap + 16-bit fixed-point split (h,l int8) ----
__global__ void k1_rowstats(const float* __restrict__ x) {
    int row = blockIdx.x, chunk = blockIdx.y;
    size_t base = (size_t)row * DCOLS + (size_t)chunk * CH1;
    const float* xr = x + base;
    int t = threadIdx.x;
    float s = 0.f;
    unsigned bm = 0u;
    #pragma unroll
    for (int it = 0; it < CH1 / 1024; it++) {
        int off = it * 1024 + t * 4;
        float4 v = *(const float4*)(xr + off);
        s += (v.x + v.y) + (v.z + v.w);
        int b;
        b = min(max(__float2int_rn(v.x) + 16, 0), 31); bm |= 1u << b;
        b = min(max(__float2int_rn(v.y) + 16, 0), 31); bm |= 1u << b;
        b = min(max(__float2int_rn(v.z) + 16, 0), 31); bm |= 1u << b;
        b = min(max(__float2int_rn(v.w) + 16, 0), 31); bm |= 1u << b;
        // q = round(x * 4096), 16-bit fixed point; split into h*256 + l (both int8)
        int q0 = min(max(__float2int_rn(v.x * 4096.f), -32640), 32639);
        int q1 = min(max(__float2int_rn(v.y * 4096.f), -32640), 32639);
        int q2 = min(max(__float2int_rn(v.z * 4096.f), -32640), 32639);
        int q3 = min(max(__float2int_rn(v.w * 4096.f), -32640), 32639);
        int h0 = (q0 + 128) >> 8, l0 = q0 - (h0 << 8);
        int h1 = (q1 + 128) >> 8, l1 = q1 - (h1 << 8);
        int h2 = (q2 + 128) >> 8, l2 = q2 - (h2 << 8);
        int h3 = (q3 + 128) >> 8, l3 = q3 - (h3 << 8);
        uint32_t hw = (h0 & 0xFF) | ((h1 & 0xFF) << 8) | ((h2 & 0xFF) << 16) | ((uint32_t)(h3 & 0xFF) << 24);
        uint32_t lw = (l0 & 0xFF) | ((l1 & 0xFF) << 8) | ((l2 & 0xFF) << 16) | ((uint32_t)(l3 & 0xFF) << 24);
        *(uint32_t*)(g_h8 + base + off) = hw;
        *(uint32_t*)(g_l8 + base + off) = lw;
    }
    __shared__ float red[256];
    __shared__ unsigned sbm[8];
    red[t] = s;
    unsigned wbm = __reduce_or_sync(0xffffffffu, bm);
    if ((t & 31) == 0) sbm[t >> 5] = wbm;
    __syncthreads();
    for (int o = 128; o > 0; o >>= 1) {
        if (t < o) red[t] += red[t + o];
        __syncthreads();
    }
    if (t == 0) {
        g_rowsum_part[row * NCHUNK1 + chunk] = red[0];
        unsigned r = 0;
        #pragma unroll
        for (int w = 0; w < 8; w++) r |= sbm[w];
        g_bitmap_part[row * NCHUNK1 + chunk] = r;
    }
}

// ---- K2 stage loader (512 threads): cp.async one 128B-row stage into buffer s%PSTG ----
__device__ __forceinline__ void issue_stage(
    int s, bool diag, int tid, uint32_t sb,
    const int8_t* A, const int8_t* B)
{
    uint32_t bofs = sb + (uint32_t)(s & (PSTG - 1)) * ABUF2;
    if (diag) {
        int cidx = tid * 2;
        int row = cidx >> 3, c0 = cidx & 7;
        const int8_t* src = A + (size_t)row * DCOLS + s * KSTG + c0 * 16;
        #pragma unroll
        for (int c = 0; c < 2; c++)
            CP_ASYNC16(bofs + swz(row * 128 + (c0 + c) * 16), src + c * 16);
    } else {
        int arr = tid >> 8;
        int t2 = tid & 255;
        int cidx = t2 * 4;
        int row = cidx >> 3, c0 = cidx & 7;
        const int8_t* src = (arr ? B : A) + (size_t)row * DCOLS + s * KSTG + c0 * 16;
        uint32_t dbase = bofs + arr * 16384;
        #pragma unroll
        for (int c = 0; c < 4; c++)
            CP_ASYNC16(dbase + swz(row * 128 + (c0 + c) * 16), src + c * 16);
    }
    CP_COMMIT();
}

// frag load for one k32 slice (kk = 0..3): 4 LDSM into buffer f
#define LOAD_FRAGS(f, kk)                                                         \
    do {                                                                          \
        uint32_t kb = (uint32_t)(kk) * 32;                                        \
        uint32_t offA0 = swz(aRow * 128 + kb + aCb);                              \
        uint32_t offA1 = swz((aRow + 16) * 128 + kb + aCb);                       \
        uint32_t offB0 = swz(bRow * 128 + kb + bCb);                              \
        uint32_t offB1 = swz((bRow + 16) * 128 + kb + bCb);                       \
        LDMX4(ah[f][0], bA + offA0);  LDMX4(ah[f][1], bA + offA1);                \
        LDMX4(bb[f][0], bB + offB0);  LDMX4(bb[f][1], bB + offB1);                \
    } while (0)

#define DO_MMAS(f)                                                                 \
    do {                                                                           \
        _Pragma("unroll")                                                          \
        for (int mt = 0; mt < 2; mt++)                                             \
            _Pragma("unroll")                                                      \
            for (int nt = 0; nt < 4; nt++) {                                       \
                int p = nt >> 1, h = (nt & 1) * 2;                                 \
                MMA_S8(acc[mt][nt], ah[f][mt], bb[f][p][h], bb[f][p][h + 1]);      \
            }                                                                      \
    } while (0)

// ---- K2: 10 unit-tile int8 GEMMs ----
// tt: 0=h0h0(d) 1=h0h1 2=h1h1(d) 3=h0l0 4=h0l1 5=h1l0 6=h1l1 7=l0l0(d) 8=l0l1 9=l1l1(d)
__global__ __launch_bounds__(512, 1) void k2_gemm() {
    extern __shared__ __align__(1024) char smem[];
    int bx = blockIdx.x;
    int tt = bx % NTILE, chunk = bx / NTILE;   // tile-fastest for L2 sharing
    static const int A0[NTILE] = {0, 0, 128, 0, 0, 128, 128, 0, 0, 128};
    static const int B0[NTILE] = {0, 128, 128, 0, 128, 0, 128, 0, 128, 128};
    int a0 = A0[tt], b0 = B0[tt];
    bool diag = (tt == 0 || tt == 2 || tt == 7 || tt == 9);
    int tid = threadIdx.x, lane = tid & 31, wid = tid >> 5;
    uint32_t sb = smem_u32(smem);
    size_t kbase = (size_t)chunk * KCH2;

    const int8_t* A = ((tt < 7) ? g_h8 : g_l8) + (size_t)a0 * DCOLS + kbase;
    const int8_t* B = ((tt < 3) ? g_h8 : g_l8) + (size_t)b0 * DCOLS + kbase;

    int acc[2][4][4];
    #pragma unroll
    for (int mt = 0; mt < 2; mt++)
        #pragma unroll
        for (int nt = 0; nt < 4; nt++)
            #pragma unroll
            for (int q = 0; q < 4; q++) acc[mt][nt][q] = 0;

    int m0w = (wid >> 2) * 32, n0w = (wid & 3) * 32;
    uint32_t aRow = (uint32_t)(m0w + (lane & 15));
    uint32_t aCb  = (uint32_t)(((lane >> 4) & 1) * 16);
    uint32_t bRow = (uint32_t)(n0w + (lane & 7) + (lane >> 4) * 8);
    uint32_t bCb  = (uint32_t)(((lane >> 3) & 1) * 16);

    issue_stage(0, diag, tid, sb, A, B);
    issue_stage(1, diag, tid, sb, A, B);
    issue_stage(2, diag, tid, sb, A, B);

    uint32_t ah[2][2][4], bb[2][2][4];

    for (int s = 0; s < NSTG; s++) {
        int rem = NSTG - 1 - s;
        if (rem >= 2)      { CP_WAIT(2); }
        else if (rem == 1) { CP_WAIT(1); }
        else               { CP_WAIT(0); }
        __syncthreads();
        if (s + 3 < NSTG) issue_stage(s + 3, diag, tid, sb, A, B);

        uint32_t bA = sb + (uint32_t)(s & (PSTG - 1)) * ABUF2;
        uint32_t bB = diag ? bA : (bA + 16384);

        LOAD_FRAGS(0, 0);
        LOAD_FRAGS(1, 1);
        DO_MMAS(0);
        LOAD_FRAGS(0, 2);
        DO_MMAS(1);
        LOAD_FRAGS(1, 3);
        DO_MMAS(0);
        DO_MMAS(1);
    }

    // epilogue: write int32 partial tile [128][128]
    int* outp = g_Gpart + (size_t)bx * 16384;
    int rb = lane >> 2, cb2 = (lane & 3) * 2;
    #pragma unroll
    for (int mt = 0; mt < 2; mt++)
        #pragma unroll
        for (int nt = 0; nt < 4; nt++) {
            int row = m0w + mt * 16 + rb;
            int col = n0w + nt * 8 + cb2;
            int2 v0; v0.x = acc[mt][nt][0]; v0.y = acc[mt][nt][1];
            int2 v1; v1.x = acc[mt][nt][2]; v1.y = acc[mt][nt][3];
            *(int2*)(outp + (size_t)row * 128 + col)       = v0;
            *(int2*)(outp + (size_t)(row + 8) * 128 + col) = v1;
        }
}

// ---- K3a: per-tile chunk reduction, exact int64, coalesced, MLP=8 ----
__global__ void k3a_reduce() {
    int e = blockIdx.x * 128 + threadIdx.x;      // 0 .. 10*16384-1
    int t = e >> 14;
    int rem = e & 16383;
    const int* p = g_Gpart + (size_t)t * 16384 + rem;   // chunk stride = NTILE*16384
    long long s0 = 0, s1 = 0, s2 = 0, s3 = 0, s4 = 0, s5 = 0, s6 = 0, s7 = 0;
    #pragma unroll 1
    for (int c = 0; c < KS2; c += 8) {
        s0 += (long long)p[(size_t)(c + 0) * (NTILE * 16384)];
        s1 += (long long)p[(size_t)(c + 1) * (NTILE * 16384)];
        s2 += (long long)p[(size_t)(c + 2) * (NTILE * 16384)];
        s3 += (long long)p[(size_t)(c + 3) * (NTILE * 16384)];
        s4 += (long long)p[(size_t)(c + 4) * (NTILE * 16384)];
        s5 += (long long)p[(size_t)(c + 5) * (NTILE * 16384)];
        s6 += (long long)p[(size_t)(c + 6) * (NTILE * 16384)];
        s7 += (long long)p[(size_t)(c + 7) * (NTILE * 16384)];
    }
    g_GtileI[e] = ((s0 + s1) + (s2 + s3)) + ((s4 + s5) + (s6 + s7));
}

// G = 2^-24 * (65536*HH + 256*(HL + LH) + LL), exact integers
#define S2INV (1.0 / 16777216.0)

// ---- K3b+K4a merged: blocks 0..191 assemble Gd; block 192 computes stats ----
__global__ void k3b_k4a() {
    if (blockIdx.x < 192) {
        int e = blockIdx.x * 256 + threadIdx.x;      // 0..49151
        int t = e >> 14;                             // quadrant 0=q00 1=q01 2=q11
        int rem = e & 16383;
        int m = rem >> 7, n = rem & 127;
        int hh  = t;
        int hla = (t == 0) ? 3 : (t == 1) ? 4 : 6;   // H_i · L_j  at [m,n]
        int hlb = (t == 0) ? 3 : (t == 1) ? 5 : 6;   // L_i · H_j  = tile[n,m]
        int ll  = 7 + t;
        long long gi = g_GtileI[hh * 16384 + rem] * 65536LL
                     + (g_GtileI[hla * 16384 + rem] + g_GtileI[hlb * 16384 + n * 128 + m]) * 256LL
                     + g_GtileI[ll * 16384 + rem];
        double s = (double)gi * S2INV;
        int gi_, gj_;
        if (t == 0)      { gi_ = m;       gj_ = n; }
        else if (t == 1) { gi_ = m;       gj_ = 128 + n; }
        else             { gi_ = 128 + m; gj_ = 128 + n; }
        g_Gd[gi_ * 256 + gj_] = s;
        if (t == 1) g_Gd[gj_ * 256 + gi_] = s;
    } else {
        int i = threadIdx.x;
        const double Dd = (double)DCOLS;
        double rs = 0.0;
        for (int c = 0; c < NCHUNK1; c++) rs += (double)g_rowsum_part[i * NCHUNK1 + c];
        double mu = rs / Dd;
        g_mu[i] = mu;
        long long gii_i;
        if (i < 128) {
            int d = i * 128 + i;
            gii_i = g_GtileI[0 * 16384 + d] * 65536LL
                  + g_GtileI[3 * 16384 + d] * 512LL
                  + g_GtileI[7 * 16384 + d];
        } else {
            int m = i - 128;
            int d = m * 128 + m;
            gii_i = g_GtileI[2 * 16384 + d] * 65536LL
                  + g_GtileI[6 * 16384 + d] * 512LL
                  + g_GtileI[9 * 16384 + d];
        }
        double gii = (double)gii_i * S2INV;
        double var = (gii - Dd * mu * mu) / (Dd - 1.0);
        g_istd[i] = 1.0 / sqrt(var);
        unsigned rw = 0;
        #pragma unroll
        for (int c = 0; c < NCHUNK1; c++) rw |= g_bitmap_part[i * NCHUNK1 + c];
        g_ru[i] = __popc(rw);
        __shared__ unsigned sw[256];
        sw[i] = rw; __syncthreads();
        for (int o = 128; o > 0; o >>= 1) {
            if (i < o) sw[i] |= sw[i + o];
            __syncthreads();
        }
        if (i == 0) g_tu = __popc(sw[0]);
    }
}

// ---- K4b: corr row sums, divide-free, 256 blocks x 256 threads ----
__global__ void k4b_corr() {
    int i = blockIdx.x, j = threadIdx.x;
    const double Dd = (double)DCOLS;
    const double invDm1 = 1.0 / (Dd - 1.0);
    double g = g_Gd[i * 256 + j];
    double cov = (g - Dd * g_mu[i] * g_mu[j]) * invDm1;
    double corr = cov * g_istd[i] * g_istd[j];
    double t = fmin(fabs(corr), 1.0);
    __shared__ double s1[256], s2[256];
    s1[j] = t; s2[j] = g; __syncthreads();
    for (int o = 128; o > 0; o >>= 1) {
        if (j < o) { s1[j] += s1[j + o]; s2[j] += s2[j + o]; }
        __syncthreads();
    }
    if (j == 0) { g_f1[i] = s1[0] * (1.0 / 256.0); g_rowGd[i] = s2[0]; }
}

// ---- K4c: final combine (1 block, O(B)) ----
__global__ void k4c_final() {
    __shared__ double srg[256], srmse[256], scand[256];
    __shared__ double sh_totG, sh_tmse;
    int i = threadIdx.x;
    const double Dd = (double)DCOLS;
    double rowG = g_rowGd[i];
    srg[i] = rowG;
    __syncthreads();
    if (i == 0) {
        double tg = 0.0;
        for (int j = 0; j < 256; j++) tg += srg[j];
        sh_totG = tg;
    }
    __syncthreads();
    double gii = g_Gd[i * 257];
    double rmse = (gii - (2.0 / 256.0) * rowG + sh_totG / 65536.0) / Dd;
    srmse[i] = rmse;
    __syncthreads();
    if (i == 0) {
        double tm = 0.0;
        for (int j = 0; j < 256; j++) tm += srmse[j];
        sh_tmse = tm;
    }
    __syncthreads();
    scand[i] = (1.0 - g_f1[i]) * (rmse / sh_tmse) * ((double)g_ru[i] / (double)g_tu);
    __syncthreads();
    if (i == 0) {
        double p = 0.0;   // max(max(c), 0)
        for (int j = 0; j < 256; j++) p = fmax(p, scand[j]);
        float pf = (float)p;
        g_p = pf;
        g_scale = (float)(1.0 / (1.0 - (double)pf));
    }
}

// ---- K5: streaming dropout, 4 float4 per thread, front-batched loads ----
__global__ void k5_dropout(const float* __restrict__ x, const float* __restrict__ noise,
                           float* __restrict__ out) {
    int t = threadIdx.x;
    size_t base = (size_t)blockIdx.x * 1024 + t;    // float4 units
    const float4* xp = (const float4*)x;
    const float4* np = (const float4*)noise;
    float4* op = (float4*)out;
    float p = g_p, sc = g_scale;
    float4 xv[4], nv[4];
    #pragma unroll
    for (int j = 0; j < 4; j++) xv[j] = xp[base + j * 256];
    #pragma unroll
    for (int j = 0; j < 4; j++) nv[j] = np[base + j * 256];
    #pragma unroll
    for (int j = 0; j < 4; j++) {
        float4 o;
        o.x = (nv[j].x >= p) ? xv[j].x * sc : 0.f;
        o.y = (nv[j].y >= p) ? xv[j].y * sc : 0.f;
        o.z = (nv[j].z >= p) ? xv[j].z * sc : 0.f;
        o.w = (nv[j].w >= p) ? xv[j].w * sc : 0.f;
        op[base + j * 256] = o;
    }
}

extern "C" void kernel_launch(void* const* d_in, const int* in_sizes, int n_in,
                              void* d_out, int out_size) {
    const float* x     = (const float*)d_in[0];
    const float* noise = (const float*)d_in[1];
    float* out = (float*)d_out;

    static bool attr_done = false;
    if (!attr_done) {
        cudaFuncSetAttribute(k2_gemm, cudaFuncAttributeMaxDynamicSharedMemorySize, PSTG * ABUF2);
        attr_done = true;
    }

    k1_rowstats<<<dim3(BROWS, NCHUNK1), 256>>>(x);       // idx 0
    kdummy<<<1, 32>>>();                                 // idx 1 (shim)
    kdummy<<<1, 32>>>();                                 // idx 2 (shim)
    k2_gemm<<<NTILE * KS2, 512, PSTG * ABUF2>>>();       // idx 3  <- ncu capture slot
    k3a_reduce<<<NTILE * 128, 128>>>();                  // idx 4
    k3b_k4a<<<193, 256>>>();                             // idx 5
    k4b_corr<<<256, 256>>>();                            // idx 6
    k4c_final<<<1, 256>>>();                             // idx 7
    size_t nvec4 = (size_t)BROWS * DCOLS / 4;            // 8388608
    k5_dropout<<<(unsigned)(nvec4 / 1024), 256>>>(x, noise, out);  // idx 8
}

// round 16
// speedup vs baseline: 1.1897x; 1.1897x over previous
#include <cuda_runtime.h>
#include <cuda_bf16.h>
#include <cstdint>

#define BROWS 256
#define DCOLS 131072
#define NCHUNK1 8
#define CH1 16384

// GEMM config (KS2=64 proven best end-to-end; bf16 HMMA path)
#define KS2  64             // K chunks
#define KCH2 2048           // K elems per chunk (per CTA)
#define KSTG 64             // K elems per stage (128B rows)
#define NSTG (KCH2 / KSTG)  // 32
#define NTILE 7             // 3 hh (sym) + 4 hl (full)
#define ABUF2 32768         // bytes per pipeline buffer (2 arrays x 16KB)
#define PSTG 4              // pipeline depth (128 KB smem)

// ---------------- scratch (static device globals; no allocation) ----------------
__device__ float         g_rowsum_part[BROWS * NCHUNK1];
__device__ unsigned      g_bitmap_part[BROWS * NCHUNK1];  // 32-bin presence words
__device__ __nv_bfloat16 g_hi[(size_t)BROWS * DCOLS];     // 64 MB
__device__ __nv_bfloat16 g_lo[(size_t)BROWS * DCOLS];     // 64 MB
__device__ float         g_Gpart[(size_t)NTILE * KS2 * 128 * 128]; // 29.4 MB
__device__ double        g_Gtile[NTILE * 16384];          // per-tile chunk-reduced
__device__ double        g_Gd[BROWS * BROWS];
__device__ double        g_mu[BROWS], g_istd[BROWS], g_f1[BROWS], g_rowGd[BROWS];
__device__ int           g_ru[BROWS], g_tu;
__device__ float         g_p;
__device__ float         g_scale;

// ---------------- portable PTX helpers (valid at compute_103) ----------------
__device__ __forceinline__ uint32_t smem_u32(const void* p) {
    uint32_t a;
    asm("{ .reg .u64 t; cvta.to.shared.u64 t, %1; cvt.u32.u64 %0, t; }" : "=r"(a) : "l"(p));
    return a;
}
__device__ __forceinline__ uint32_t swz(uint32_t off) { return off ^ ((off >> 3) & 0x70); }

#define CP_ASYNC16(dst, src) \
    asm volatile("cp.async.cg.shared.global [%0], [%1], 16;" :: "r"(dst), "l"(src) : "memory")
#define CP_COMMIT() asm volatile("cp.async.commit_group;" ::: "memory")
#define CP_WAIT(n)  asm volatile("cp.async.wait_group %0;" :: "n"(n) : "memory")

#define LDMX4(R, addr) \
    asm volatile("ldmatrix.sync.aligned.m8n8.x4.shared.b16 {%0,%1,%2,%3}, [%4];" \
        : "=r"((R)[0]), "=r"((R)[1]), "=r"((R)[2]), "=r"((R)[3]) : "r"(addr))

#define MMA_BF16(D, A, B0, B1) \
    asm volatile("mma.sync.aligned.m16n8k16.row.col.f32.bf16.bf16.f32 " \
        "{%0,%1,%2,%3}, {%4,%5,%6,%7}, {%8,%9}, {%0,%1,%2,%3};" \
        : "+f"((D)[0]), "+f"((D)[1]), "+f"((D)[2]), "+f"((D)[3]) \
        : "r"((A)[0]), "r"((A)[1]), "r"((A)[2]), "r"((A)[3]), "r"(B0), "r"(B1))

// ---- dummy: shims so k2 lands at the ncu capture slot (launch index 3) ----
__global__ void kdummy() {}

// ---- K1: row sums + 32-bin rounded-value bitmap + hi/lo bf16 split ----
__global__ void k1_rowstats(const float* __restrict__ x) {
    int row = blockIdx.x, chunk = blockIdx.y;
    size_t base = (size_t)row * DCOLS + (size_t)chunk * CH1;
    const float* xr = x + base;
    int t = threadIdx.x;
    float s = 0.f;
    unsigned bm = 0u;
    #pragma unroll
    for (int it = 0; it < CH1 / 1024; it++) {
        int off = it * 1024 + t * 4;
        float4 v = *(const float4*)(xr + off);
        s += (v.x + v.y) + (v.z + v.w);
        int b;
        b = min(max(__float2int_rn(v.x) + 16, 0), 31); bm |= 1u << b;
        b = min(max(__float2int_rn(v.y) + 16, 0), 31); bm |= 1u << b;
        b = min(max(__float2int_rn(v.z) + 16, 0), 31); bm |= 1u << b;
        b = min(max(__float2int_rn(v.w) + 16, 0), 31); bm |= 1u << b;
        __nv_bfloat162 h01b = __float22bfloat162_rn(make_float2(v.x, v.y));
        __nv_bfloat162 h23b = __float22bfloat162_rn(make_float2(v.z, v.w));
        uint32_t h01 = *(uint32_t*)&h01b;
        uint32_t h23 = *(uint32_t*)&h23b;
        float hx = __uint_as_float(h01 << 16);
        float hy = __uint_as_float(h01 & 0xFFFF0000u);
        float hz = __uint_as_float(h23 << 16);
        float hw = __uint_as_float(h23 & 0xFFFF0000u);
        __nv_bfloat162 l01b = __float22bfloat162_rn(make_float2(v.x - hx, v.y - hy));
        __nv_bfloat162 l23b = __float22bfloat162_rn(make_float2(v.z - hz, v.w - hw));
        uint2 hv, lv;
        hv.x = h01; hv.y = h23;
        lv.x = *(uint32_t*)&l01b; lv.y = *(uint32_t*)&l23b;
        *(uint2*)(g_hi + base + off) = hv;
        *(uint2*)(g_lo + base + off) = lv;
    }
    __shared__ float red[256];
    __shared__ unsigned sbm[8];
    red[t] = s;
    unsigned wbm = __reduce_or_sync(0xffffffffu, bm);
    if ((t & 31) == 0) sbm[t >> 5] = wbm;
    __syncthreads();
    for (int o = 128; o > 0; o >>= 1) {
        if (t < o) red[t] += red[t + o];
        __syncthreads();
    }
    if (t == 0) {
        g_rowsum_part[row * NCHUNK1 + chunk] = red[0];
        unsigned r = 0;
        #pragma unroll
        for (int w = 0; w < 8; w++) r |= sbm[w];
        g_bitmap_part[row * NCHUNK1 + chunk] = r;
    }
}

// ---- K2 stage loader (512 threads): cp.async one 64-k stage into buffer s%PSTG ----
__device__ __forceinline__ void issue_stage(
    int s, bool diag, int tid, uint32_t sb,
    const __nv_bfloat16* A, const __nv_bfloat16* B)
{
    uint32_t bofs = sb + (uint32_t)(s & (PSTG - 1)) * ABUF2;
    if (diag) {
        int cidx = tid * 2;
        int row = cidx >> 3, c0 = cidx & 7;
        const __nv_bfloat16* src = A + (size_t)row * DCOLS + s * KSTG + c0 * 8;
        #pragma unroll
        for (int c = 0; c < 2; c++)
            CP_ASYNC16(bofs + swz(row * 128 + (c0 + c) * 16), src + c * 8);
    } else {
        int arr = tid >> 8;
        int t2 = tid & 255;
        int cidx = t2 * 4;
        int row = cidx >> 3, c0 = cidx & 7;
        const __nv_bfloat16* src = (arr ? B : A) + (size_t)row * DCOLS + s * KSTG + c0 * 8;
        uint32_t dbase = bofs + arr * 16384;
        #pragma unroll
        for (int c = 0; c < 4; c++)
            CP_ASYNC16(dbase + swz(row * 128 + (c0 + c) * 16), src + c * 8);
    }
    CP_COMMIT();
}

// frag load for one k16 slice (kk = 0..3): 4 LDSM into buffer f
#define LOAD_FRAGS(f, kk)                                                         \
    do {                                                                          \
        uint32_t kb = (uint32_t)(kk) * 32;                                        \
        uint32_t offA0 = swz(aRow * 128 + kb + aCb);                              \
        uint32_t offA1 = swz((aRow + 16) * 128 + kb + aCb);                       \
        uint32_t offB0 = swz(bRow * 128 + kb + bCb);                              \
        uint32_t offB1 = swz((bRow + 16) * 128 + kb + bCb);                       \
        LDMX4(ah[f][0], bA + offA0);  LDMX4(ah[f][1], bA + offA1);                \
        LDMX4(bb[f][0], bB + offB0);  LDMX4(bb[f][1], bB + offB1);                \
    } while (0)

#define DO_MMAS(f)                                                                 \
    do {                                                                           \
        _Pragma("unroll")                                                          \
        for (int mt = 0; mt < 2; mt++)                                             \
            _Pragma("unroll")                                                      \
            for (int nt = 0; nt < 4; nt++) {                                       \
                int p = nt >> 1, h = (nt & 1) * 2;                                 \
                MMA_BF16(acc[mt][nt], ah[f][mt], bb[f][p][h], bb[f][p][h + 1]);    \
            }                                                                      \
    } while (0)

// ---- K2: 7 unit-tile GEMMs; diag tiles compute only upper-triangle warp tiles ----
__global__ __launch_bounds__(512, 1) void k2_gemm() {
    extern __shared__ __align__(1024) char smem[];
    int bx = blockIdx.x;
    int tt = bx % NTILE, chunk = bx / NTILE;   // tile-fastest for L2 sharing
    int a0, b0;
    if      (tt == 0) { a0 = 0;   b0 = 0;   }
    else if (tt == 1) { a0 = 0;   b0 = 128; }
    else if (tt == 2) { a0 = 128; b0 = 128; }
    else if (tt == 3) { a0 = 0;   b0 = 0;   }
    else if (tt == 4) { a0 = 0;   b0 = 128; }
    else if (tt == 5) { a0 = 128; b0 = 0;   }
    else              { a0 = 128; b0 = 128; }
    bool diag = (tt == 0 || tt == 2);
    int tid = threadIdx.x, lane = tid & 31, wid = tid >> 5;
    uint32_t sb = smem_u32(smem);
    size_t kbase = (size_t)chunk * KCH2;

    const __nv_bfloat16* A = g_hi + (size_t)a0 * DCOLS + kbase;
    const __nv_bfloat16* B = ((tt < 3) ? g_hi : g_lo) + (size_t)b0 * DCOLS + kbase;

    // warp-tile mapping: full tiles use 4x4 grid; diag tiles use 10 upper-tri
    // tiles remapped to wids 0..9 (SMSP loads 3/3/2/2 instead of 4/4/4/4)
    int mi, ni;
    bool active = true;
    if (diag) {
        if (wid < 10) {
            static const int MIa[10] = {0,0,0,0,1,1,1,2,2,3};
            static const int NIa[10] = {0,1,2,3,1,2,3,2,3,3};
            mi = MIa[wid]; ni = NIa[wid];
        } else {
            active = false; mi = 0; ni = 0;
        }
    } else {
        mi = wid >> 2; ni = wid & 3;
    }
    int m0w = mi * 32, n0w = ni * 32;

    float acc[2][4][4];
    #pragma unroll
    for (int mt = 0; mt < 2; mt++)
        #pragma unroll
        for (int nt = 0; nt < 4; nt++)
            #pragma unroll
            for (int q = 0; q < 4; q++) acc[mt][nt][q] = 0.f;

    uint32_t aRow = (uint32_t)(m0w + (lane & 15));
    uint32_t aCb  = (uint32_t)(((lane >> 4) & 1) * 16);
    uint32_t bRow = (uint32_t)(n0w + (lane & 7) + (lane >> 4) * 8);
    uint32_t bCb  = (uint32_t)(((lane >> 3) & 1) * 16);

    issue_stage(0, diag, tid, sb, A, B);
    issue_stage(1, diag, tid, sb, A, B);
    issue_stage(2, diag, tid, sb, A, B);

    uint32_t ah[2][2][4], bb[2][2][4];   // double-buffered fragments

    for (int s = 0; s < NSTG; s++) {
        int rem = NSTG - 1 - s;
        if (rem >= 2)      { CP_WAIT(2); }
        else if (rem == 1) { CP_WAIT(1); }
        else               { CP_WAIT(0); }
        __syncthreads();
        if (s + 3 < NSTG) issue_stage(s + 3, diag, tid, sb, A, B);

        if (active) {
            uint32_t bA = sb + (uint32_t)(s & (PSTG - 1)) * ABUF2;
            uint32_t bB = diag ? bA : (bA + 16384);

            LOAD_FRAGS(0, 0);
            LOAD_FRAGS(1, 1);
            DO_MMAS(0);
            LOAD_FRAGS(0, 2);
            DO_MMAS(1);
            LOAD_FRAGS(1, 3);
            DO_MMAS(0);
            DO_MMAS(1);
        }
    }

    // epilogue: write fp32 partial tile (upper-triangle only for diag tiles)
    if (active) {
        float* outp = g_Gpart + (size_t)bx * 16384;
        int rb = lane >> 2, cb2 = (lane & 3) * 2;
        #pragma unroll
        for (int mt = 0; mt < 2; mt++)
            #pragma unroll
            for (int nt = 0; nt < 4; nt++) {
                int row = m0w + mt * 16 + rb;
                int col = n0w + nt * 8 + cb2;
                float2 v0; v0.x = acc[mt][nt][0]; v0.y = acc[mt][nt][1];
                float2 v1; v1.x = acc[mt][nt][2]; v1.y = acc[mt][nt][3];
                *(float2*)(outp + (size_t)row * 128 + col)       = v0;
                *(float2*)(outp + (size_t)(row + 8) * 128 + col) = v1;
            }
    }
}

// ---- K3a: per-tile chunk reduction, fully coalesced, fp64, MLP=8 ----
__global__ void k3a_reduce() {
    int e = blockIdx.x * 128 + threadIdx.x;      // 0 .. 7*16384-1
    int t = e >> 14;                             // tile 0..6
    int rem = e & 16383;
    const float* p = g_Gpart + (size_t)t * 16384 + rem;   // chunk stride = NTILE*16384
    double s0 = 0, s1 = 0, s2 = 0, s3 = 0, s4 = 0, s5 = 0, s6 = 0, s7 = 0;
    #pragma unroll 1
    for (int c = 0; c < KS2; c += 8) {
        s0 += (double)p[(size_t)(c + 0) * (NTILE * 16384)];
        s1 += (double)p[(size_t)(c + 1) * (NTILE * 16384)];
        s2 += (double)p[(size_t)(c + 2) * (NTILE * 16384)];
        s3 += (double)p[(size_t)(c + 3) * (NTILE * 16384)];
        s4 += (double)p[(size_t)(c + 4) * (NTILE * 16384)];
        s5 += (double)p[(size_t)(c + 5) * (NTILE * 16384)];
        s6 += (double)p[(size_t)(c + 6) * (NTILE * 16384)];
        s7 += (double)p[(size_t)(c + 7) * (NTILE * 16384)];
    }
    g_Gtile[e] = ((s0 + s1) + (s2 + s3)) + ((s4 + s5) + (s6 + s7));
}

// ---- K3b+K4a merged: blocks 0..191 assemble G; block 192 computes stats ----
__global__ void k3b_k4a() {
    if (blockIdx.x < 192) {
        int e = blockIdx.x * 256 + threadIdx.x;      // 0..49151
        int t = e >> 14;                             // sym quadrant 0..2
        int rem = e & 16383;
        int m = rem >> 7, n = rem & 127;
        // diag HH tiles only have upper triangle written: mirror if below
        int remHH = (t == 1 || m <= n) ? rem : (n * 128 + m);
        int pa = (t == 0) ? 3 : (t == 1) ? 4 : 6;    // P[m,n] tile
        int pb = (t == 0) ? 3 : (t == 1) ? 5 : 6;    // Pᵀ source tile (read [n,m])
        double s = g_Gtile[t * 16384 + remHH]
                 + g_Gtile[pa * 16384 + rem]
                 + g_Gtile[pb * 16384 + n * 128 + m];
        int gi, gj;
        if (t == 0)      { gi = m;       gj = n; }
        else if (t == 1) { gi = m;       gj = 128 + n; }
        else             { gi = 128 + m; gj = 128 + n; }
        g_Gd[gi * 256 + gj] = s;
        if (t == 1) g_Gd[gj * 256 + gi] = s;
    } else {
        // stats: reads only g_Gtile (independent of assembly blocks)
        int i = threadIdx.x;
        const double Dd = (double)DCOLS;
        double rs = 0.0;
        for (int c = 0; c < NCHUNK1; c++) rs += (double)g_rowsum_part[i * NCHUNK1 + c];
        double mu = rs / Dd;
        g_mu[i] = mu;
        // gii via same 3-term left-to-right order as assembly at (i,i)
        double gii;
        if (i < 128) {
            int d = i * 128 + i;
            gii = g_Gtile[0 * 16384 + d] + g_Gtile[3 * 16384 + d] + g_Gtile[3 * 16384 + d];
        } else {
            int m = i - 128;
            int d = m * 128 + m;
            gii = g_Gtile[2 * 16384 + d] + g_Gtile[6 * 16384 + d] + g_Gtile[6 * 16384 + d];
        }
        double var = (gii - Dd * mu * mu) / (Dd - 1.0);
        g_istd[i] = 1.0 / sqrt(var);
        unsigned rw = 0;
        #pragma unroll
        for (int c = 0; c < NCHUNK1; c++) rw |= g_bitmap_part[i * NCHUNK1 + c];
        g_ru[i] = __popc(rw);
        __shared__ unsigned sw[256];
        sw[i] = rw; __syncthreads();
        for (int o = 128; o > 0; o >>= 1) {
            if (i < o) sw[i] |= sw[i + o];
            __syncthreads();
        }
        if (i == 0) g_tu = __popc(sw[0]);
    }
}

// ---- K4b: corr row sums, divide-free, 256 blocks x 256 threads ----
__global__ void k4b_corr() {
    int i = blockIdx.x, j = threadIdx.x;
    const double Dd = (double)DCOLS;
    const double invDm1 = 1.0 / (Dd - 1.0);
    double g = g_Gd[i * 256 + j];
    double cov = (g - Dd * g_mu[i] * g_mu[j]) * invDm1;
    double corr = cov * g_istd[i] * g_istd[j];
    double t = fmin(fabs(corr), 1.0);
    __shared__ double s1[256], s2[256];
    s1[j] = t; s2[j] = g; __syncthreads();
    for (int o = 128; o > 0; o >>= 1) {
        if (j < o) { s1[j] += s1[j + o]; s2[j] += s2[j + o]; }
        __syncthreads();
    }
    if (j == 0) { g_f1[i] = s1[0] * (1.0 / 256.0); g_rowGd[i] = s2[0]; }
}

// ---- K4c: final combine (1 block, O(B)) ----
__global__ void k4c_final() {
    __shared__ double srg[256], srmse[256], scand[256];
    __shared__ double sh_totG, sh_tmse;
    int i = threadIdx.x;
    const double Dd = (double)DCOLS;
    double rowG = g_rowGd[i];
    srg[i] = rowG;
    __syncthreads();
    if (i == 0) {
        double tg = 0.0;
        for (int j = 0; j < 256; j++) tg += srg[j];
        sh_totG = tg;
    }
    __syncthreads();
    double gii = g_Gd[i * 257];
    double rmse = (gii - (2.0 / 256.0) * rowG + sh_totG / 65536.0) / Dd;
    srmse[i] = rmse;
    __syncthreads();
    if (i == 0) {
        double tm = 0.0;
        for (int j = 0; j < 256; j++) tm += srmse[j];
        sh_tmse = tm;
    }
    __syncthreads();
    scand[i] = (1.0 - g_f1[i]) * (rmse / sh_tmse) * ((double)g_ru[i] / (double)g_tu);
    __syncthreads();
    if (i == 0) {
        double p = 0.0;   // max(max(c), 0)
        for (int j = 0; j < 256; j++) p = fmax(p, scand[j]);
        float pf = (float)p;
        g_p = pf;
        g_scale = (float)(1.0 / (1.0 - (double)pf));
    }
}

// ---- K5: streaming dropout, 4 float4 per thread, front-batched loads ----
__global__ void k5_dropout(const float* __restrict__ x, const float* __restrict__ noise,
                           float* __restrict__ out) {
    int t = threadIdx.x;
    size_t base = (size_t)blockIdx.x * 1024 + t;    // float4 units
    const float4* xp = (const float4*)x;
    const float4* np = (const float4*)noise;
    float4* op = (float4*)out;
    float p = g_p, sc = g_scale;
    float4 xv[4], nv[4];
    #pragma unroll
    for (int j = 0; j < 4; j++) xv[j] = xp[base + j * 256];
    #pragma unroll
    for (int j = 0; j < 4; j++) nv[j] = np[base + j * 256];
    #pragma unroll
    for (int j = 0; j < 4; j++) {
        float4 o;
        o.x = (nv[j].x >= p) ? xv[j].x * sc : 0.f;
        o.y = (nv[j].y >= p) ? xv[j].y * sc : 0.f;
        o.z = (nv[j].z >= p) ? xv[j].z * sc : 0.f;
        o.w = (nv[j].w >= p) ? xv[j].w * sc : 0.f;
        op[base + j * 256] = o;
    }
}

extern "C" void kernel_launch(void* const* d_in, const int* in_sizes, int n_in,
                              void* d_out, int out_size) {
    const float* x     = (const float*)d_in[0];
    const float* noise = (const float*)d_in[1];
    float* out = (float*)d_out;

    static bool attr_done = false;
    if (!attr_done) {
        cudaFuncSetAttribute(k2_gemm, cudaFuncAttributeMaxDynamicSharedMemorySize, PSTG * ABUF2);
        attr_done = true;
    }

    k1_rowstats<<<dim3(BROWS, NCHUNK1), 256>>>(x);       // idx 0
    kdummy<<<1, 32>>>();                                 // idx 1 (shim)
    kdummy<<<1, 32>>>();                                 // idx 2 (shim)
    k2_gemm<<<NTILE * KS2, 512, PSTG * ABUF2>>>();       // idx 3  <- ncu capture slot
    k3a_reduce<<<NTILE * 128, 128>>>();                  // idx 4
    k3b_k4a<<<193, 256>>>();                             // idx 5
    k4b_corr<<<256, 256>>>();                            // idx 6
    k4c_final<<<1, 256>>>();                             // idx 7
    size_t nvec4 = (size_t)BROWS * DCOLS / 4;            // 8388608
    k5_dropout<<<(unsigned)(nvec4 / 1024), 256>>>(x, noise, out);  // idx 8
}

// round 17
// speedup vs baseline: 1.6693x; 1.4032x over previous
#include <cuda_runtime.h>
#include <cuda_bf16.h>
#include <cstdint>

#define BROWS 256
#define DCOLS 131072
#define NCHUNK1 8
#define CH1 16384

// GEMM config (KS2=64 proven best end-to-end; bf16 HMMA path; k2 measured 125us)
#define KS2  64             // K chunks
#define KCH2 2048           // K elems per chunk (per CTA)
#define KSTG 64             // K elems per stage (128B rows)
#define NSTG (KCH2 / KSTG)  // 32
#define NTILE 7             // 3 hh (sym) + 4 hl (full)
#define ABUF2 32768         // bytes per pipeline buffer (2 arrays x 16KB)
#define PSTG 4              // pipeline depth (128 KB smem)

// ---------------- scratch (static device globals; no allocation) ----------------
__device__ float         g_rowsum_part[BROWS * NCHUNK1];
__device__ unsigned      g_bitmap_part[BROWS * NCHUNK1];  // 32-bin presence words
__device__ __nv_bfloat16 g_hi[(size_t)BROWS * DCOLS];     // 64 MB
__device__ __nv_bfloat16 g_lo[(size_t)BROWS * DCOLS];     // 64 MB
__device__ float         g_Gpart[(size_t)NTILE * KS2 * 128 * 128]; // 29.4 MB
__device__ double        g_Gtile[NTILE * 16384];          // per-tile chunk-reduced
__device__ double        g_Gd[BROWS * BROWS];
__device__ double        g_mu[BROWS], g_istd[BROWS], g_f1[BROWS], g_rowGd[BROWS];
__device__ int           g_ru[BROWS], g_tu;
__device__ float         g_p;
__device__ float         g_scale;

// ---------------- portable PTX helpers (valid at compute_103) ----------------
__device__ __forceinline__ uint32_t smem_u32(const void* p) {
    uint32_t a;
    asm("{ .reg .u64 t; cvta.to.shared.u64 t, %1; cvt.u32.u64 %0, t; }" : "=r"(a) : "l"(p));
    return a;
}
__device__ __forceinline__ uint32_t swz(uint32_t off) { return off ^ ((off >> 3) & 0x70); }

#define CP_ASYNC16(dst, src) \
    asm volatile("cp.async.cg.shared.global [%0], [%1], 16;" :: "r"(dst), "l"(src) : "memory")
#define CP_COMMIT() asm volatile("cp.async.commit_group;" ::: "memory")
#define CP_WAIT(n)  asm volatile("cp.async.wait_group %0;" :: "n"(n) : "memory")

#define LDMX4(R, addr) \
    asm volatile("ldmatrix.sync.aligned.m8n8.x4.shared.b16 {%0,%1,%2,%3}, [%4];" \
        : "=r"((R)[0]), "=r"((R)[1]), "=r"((R)[2]), "=r"((R)[3]) : "r"(addr))

#define MMA_BF16(D, A, B0, B1) \
    asm volatile("mma.sync.aligned.m16n8k16.row.col.f32.bf16.bf16.f32 " \
        "{%0,%1,%2,%3}, {%4,%5,%6,%7}, {%8,%9}, {%0,%1,%2,%3};" \
        : "+f"((D)[0]), "+f"((D)[1]), "+f"((D)[2]), "+f"((D)[3]) \
        : "r"((A)[0]), "r"((A)[1]), "r"((A)[2]), "r"((A)[3]), "r"(B0), "r"(B1))

// ---- K1: row sums + 32-bin rounded-value bitmap + hi/lo bf16 split ----
__global__ void k1_rowstats(const float* __restrict__ x) {
    int row = blockIdx.x, chunk = blockIdx.y;
    size_t base = (size_t)row * DCOLS + (size_t)chunk * CH1;
    const float* xr = x + base;
    int t = threadIdx.x;
    float s = 0.f;
    unsigned bm = 0u;
    #pragma unroll
    for (int it = 0; it < CH1 / 1024; it++) {
        int off = it * 1024 + t * 4;
        float4 v = *(const float4*)(xr + off);
        s += (v.x + v.y) + (v.z + v.w);
        int b;
        b = min(max(__float2int_rn(v.x) + 16, 0), 31); bm |= 1u << b;
        b = min(max(__float2int_rn(v.y) + 16, 0), 31); bm |= 1u << b;
        b = min(max(__float2int_rn(v.z) + 16, 0), 31); bm |= 1u << b;
        b = min(max(__float2int_rn(v.w) + 16, 0), 31); bm |= 1u << b;
        __nv_bfloat162 h01b = __float22bfloat162_rn(make_float2(v.x, v.y));
        __nv_bfloat162 h23b = __float22bfloat162_rn(make_float2(v.z, v.w));
        uint32_t h01 = *(uint32_t*)&h01b;
        uint32_t h23 = *(uint32_t*)&h23b;
        float hx = __uint_as_float(h01 << 16);
        float hy = __uint_as_float(h01 & 0xFFFF0000u);
        float hz = __uint_as_float(h23 << 16);
        float hw = __uint_as_float(h23 & 0xFFFF0000u);
        __nv_bfloat162 l01b = __float22bfloat162_rn(make_float2(v.x - hx, v.y - hy));
        __nv_bfloat162 l23b = __float22bfloat162_rn(make_float2(v.z - hz, v.w - hw));
        uint2 hv, lv;
        hv.x = h01; hv.y = h23;
        lv.x = *(uint32_t*)&l01b; lv.y = *(uint32_t*)&l23b;
        *(uint2*)(g_hi + base + off) = hv;
        *(uint2*)(g_lo + base + off) = lv;
    }
    __shared__ float red[256];
    __shared__ unsigned sbm[8];
    red[t] = s;
    unsigned wbm = __reduce_or_sync(0xffffffffu, bm);
    if ((t & 31) == 0) sbm[t >> 5] = wbm;
    __syncthreads();
    for (int o = 128; o > 0; o >>= 1) {
        if (t < o) red[t] += red[t + o];
        __syncthreads();
    }
    if (t == 0) {
        g_rowsum_part[row * NCHUNK1 + chunk] = red[0];
        unsigned r = 0;
        #pragma unroll
        for (int w = 0; w < 8; w++) r |= sbm[w];
        g_bitmap_part[row * NCHUNK1 + chunk] = r;
    }
}

// ---- K2 stage loader (512 threads): cp.async one 64-k stage into buffer s%PSTG ----
__device__ __forceinline__ void issue_stage(
    int s, bool diag, int tid, uint32_t sb,
    const __nv_bfloat16* A, const __nv_bfloat16* B)
{
    uint32_t bofs = sb + (uint32_t)(s & (PSTG - 1)) * ABUF2;
    if (diag) {
        int cidx = tid * 2;
        int row = cidx >> 3, c0 = cidx & 7;
        const __nv_bfloat16* src = A + (size_t)row * DCOLS + s * KSTG + c0 * 8;
        #pragma unroll
        for (int c = 0; c < 2; c++)
            CP_ASYNC16(bofs + swz(row * 128 + (c0 + c) * 16), src + c * 8);
    } else {
        int arr = tid >> 8;
        int t2 = tid & 255;
        int cidx = t2 * 4;
        int row = cidx >> 3, c0 = cidx & 7;
        const __nv_bfloat16* src = (arr ? B : A) + (size_t)row * DCOLS + s * KSTG + c0 * 8;
        uint32_t dbase = bofs + arr * 16384;
        #pragma unroll
        for (int c = 0; c < 4; c++)
            CP_ASYNC16(dbase + swz(row * 128 + (c0 + c) * 16), src + c * 8);
    }
    CP_COMMIT();
}

// frag load for one k16 slice (kk = 0..3): 4 LDSM into buffer f
#define LOAD_FRAGS(f, kk)                                                         \
    do {                                                                          \
        uint32_t kb = (uint32_t)(kk) * 32;                                        \
        uint32_t offA0 = swz(aRow * 128 + kb + aCb);                              \
        uint32_t offA1 = swz((aRow + 16) * 128 + kb + aCb);                       \
        uint32_t offB0 = swz(bRow * 128 + kb + bCb);                              \
        uint32_t offB1 = swz((bRow + 16) * 128 + kb + bCb);                       \
        LDMX4(ah[f][0], bA + offA0);  LDMX4(ah[f][1], bA + offA1);                \
        LDMX4(bb[f][0], bB + offB0);  LDMX4(bb[f][1], bB + offB1);                \
    } while (0)

#define DO_MMAS(f)                                                                 \
    do {                                                                           \
        _Pragma("unroll")                                                          \
        for (int mt = 0; mt < 2; mt++)                                             \
            _Pragma("unroll")                                                      \
            for (int nt = 0; nt < 4; nt++) {                                       \
                int p = nt >> 1, h = (nt & 1) * 2;                                 \
                MMA_BF16(acc[mt][nt], ah[f][mt], bb[f][p][h], bb[f][p][h + 1]);    \
            }                                                                      \
    } while (0)

// ---- K2: 7 unit-tile GEMMs: tt 0..2 = Hi·Hiᵀ sym tiles, tt 3..6 = Hi·Loᵀ full ----
__global__ __launch_bounds__(512, 1) void k2_gemm() {
    extern __shared__ __align__(1024) char smem[];
    int bx = blockIdx.x;
    int tt = bx % NTILE, chunk = bx / NTILE;   // tile-fastest for L2 sharing
    int a0, b0;
    if      (tt == 0) { a0 = 0;   b0 = 0;   }
    else if (tt == 1) { a0 = 0;   b0 = 128; }
    else if (tt == 2) { a0 = 128; b0 = 128; }
    else if (tt == 3) { a0 = 0;   b0 = 0;   }
    else if (tt == 4) { a0 = 0;   b0 = 128; }
    else if (tt == 5) { a0 = 128; b0 = 0;   }
    else              { a0 = 128; b0 = 128; }
    bool diag = (tt == 0 || tt == 2);
    int tid = threadIdx.x, lane = tid & 31, wid = tid >> 5;
    uint32_t sb = smem_u32(smem);
    size_t kbase = (size_t)chunk * KCH2;

    const __nv_bfloat16* A = g_hi + (size_t)a0 * DCOLS + kbase;
    const __nv_bfloat16* B = ((tt < 3) ? g_hi : g_lo) + (size_t)b0 * DCOLS + kbase;

    float acc[2][4][4];
    #pragma unroll
    for (int mt = 0; mt < 2; mt++)
        #pragma unroll
        for (int nt = 0; nt < 4; nt++)
            #pragma unroll
            for (int q = 0; q < 4; q++) acc[mt][nt][q] = 0.f;

    int m0w = (wid >> 2) * 32, n0w = (wid & 3) * 32;
    uint32_t aRow = (uint32_t)(m0w + (lane & 15));
    uint32_t aCb  = (uint32_t)(((lane >> 4) & 1) * 16);
    uint32_t bRow = (uint32_t)(n0w + (lane & 7) + (lane >> 4) * 8);
    uint32_t bCb  = (uint32_t)(((lane >> 3) & 1) * 16);

    issue_stage(0, diag, tid, sb, A, B);
    issue_stage(1, diag, tid, sb, A, B);
    issue_stage(2, diag, tid, sb, A, B);

    uint32_t ah[2][2][4], bb[2][2][4];   // double-buffered fragments

    for (int s = 0; s < NSTG; s++) {
        int rem = NSTG - 1 - s;
        if (rem >= 2)      { CP_WAIT(2); }
        else if (rem == 1) { CP_WAIT(1); }
        else               { CP_WAIT(0); }
        __syncthreads();
        if (s + 3 < NSTG) issue_stage(s + 3, diag, tid, sb, A, B);

        uint32_t bA = sb + (uint32_t)(s & (PSTG - 1)) * ABUF2;
        uint32_t bB = diag ? bA : (bA + 16384);

        LOAD_FRAGS(0, 0);
        LOAD_FRAGS(1, 1);
        DO_MMAS(0);
        LOAD_FRAGS(0, 2);
        DO_MMAS(1);
        LOAD_FRAGS(1, 3);
        DO_MMAS(0);
        DO_MMAS(1);
    }

    // epilogue: write fp32 partial tile [128][128]
    float* outp = g_Gpart + (size_t)bx * 16384;
    int rb = lane >> 2, cb2 = (lane & 3) * 2;
    #pragma unroll
    for (int mt = 0; mt < 2; mt++)
        #pragma unroll
        for (int nt = 0; nt < 4; nt++) {
            int row = m0w + mt * 16 + rb;
            int col = n0w + nt * 8 + cb2;
            float2 v0; v0.x = acc[mt][nt][0]; v0.y = acc[mt][nt][1];
            float2 v1; v1.x = acc[mt][nt][2]; v1.y = acc[mt][nt][3];
            *(float2*)(outp + (size_t)row * 128 + col)       = v0;
            *(float2*)(outp + (size_t)(row + 8) * 128 + col) = v1;
        }
}

// ---- K3a: per-tile chunk reduction, fully coalesced, fp64, MLP=8 ----
__global__ void k3a_reduce() {
    int e = blockIdx.x * 128 + threadIdx.x;      // 0 .. 7*16384-1
    int t = e >> 14;                             // tile 0..6
    int rem = e & 16383;
    const float* p = g_Gpart + (size_t)t * 16384 + rem;   // chunk stride = NTILE*16384
    double s0 = 0, s1 = 0, s2 = 0, s3 = 0, s4 = 0, s5 = 0, s6 = 0, s7 = 0;
    #pragma unroll 1
    for (int c = 0; c < KS2; c += 8) {
        s0 += (double)p[(size_t)(c + 0) * (NTILE * 16384)];
        s1 += (double)p[(size_t)(c + 1) * (NTILE * 16384)];
        s2 += (double)p[(size_t)(c + 2) * (NTILE * 16384)];
        s3 += (double)p[(size_t)(c + 3) * (NTILE * 16384)];
        s4 += (double)p[(size_t)(c + 4) * (NTILE * 16384)];
        s5 += (double)p[(size_t)(c + 5) * (NTILE * 16384)];
        s6 += (double)p[(size_t)(c + 6) * (NTILE * 16384)];
        s7 += (double)p[(size_t)(c + 7) * (NTILE * 16384)];
    }
    g_Gtile[e] = ((s0 + s1) + (s2 + s3)) + ((s4 + s5) + (s6 + s7));
}

// ---- K3b+K4a merged: blocks 0..191 assemble G; block 192 computes stats ----
__global__ void k3b_k4a() {
    if (blockIdx.x < 192) {
        int e = blockIdx.x * 256 + threadIdx.x;      // 0..49151
        int t = e >> 14;                             // sym quadrant 0..2
        int rem = e & 16383;
        int m = rem >> 7, n = rem & 127;
        int pa = (t == 0) ? 3 : (t == 1) ? 4 : 6;    // P[m,n] tile
        int pb = (t == 0) ? 3 : (t == 1) ? 5 : 6;    // Pᵀ source tile (read [n,m])
        double s = g_Gtile[t * 16384 + rem]
                 + g_Gtile[pa * 16384 + rem]
                 + g_Gtile[pb * 16384 + n * 128 + m];
        int gi, gj;
        if (t == 0)      { gi = m;       gj = n; }
        else if (t == 1) { gi = m;       gj = 128 + n; }
        else             { gi = 128 + m; gj = 128 + n; }
        g_Gd[gi * 256 + gj] = s;
        if (t == 1) g_Gd[gj * 256 + gi] = s;
    } else {
        // stats: reads only g_Gtile (independent of assembly blocks)
        int i = threadIdx.x;
        const double Dd = (double)DCOLS;
        double rs = 0.0;
        for (int c = 0; c < NCHUNK1; c++) rs += (double)g_rowsum_part[i * NCHUNK1 + c];
        double mu = rs / Dd;
        g_mu[i] = mu;
        // gii via same 3-term left-to-right order as assembly at (i,i)
        double gii;
        if (i < 128) {
            int d = i * 128 + i;
            gii = g_Gtile[0 * 16384 + d] + g_Gtile[3 * 16384 + d] + g_Gtile[3 * 16384 + d];
        } else {
            int m = i - 128;
            int d = m * 128 + m;
            gii = g_Gtile[2 * 16384 + d] + g_Gtile[6 * 16384 + d] + g_Gtile[6 * 16384 + d];
        }
        double var = (gii - Dd * mu * mu) / (Dd - 1.0);
        g_istd[i] = 1.0 / sqrt(var);
        unsigned rw = 0;
        #pragma unroll
        for (int c = 0; c < NCHUNK1; c++) rw |= g_bitmap_part[i * NCHUNK1 + c];
        g_ru[i] = __popc(rw);
        __shared__ unsigned sw[256];
        sw[i] = rw; __syncthreads();
        for (int o = 128; o > 0; o >>= 1) {
            if (i < o) sw[i] |= sw[i + o];
            __syncthreads();
        }
        if (i == 0) g_tu = __popc(sw[0]);
    }
}

// ---- K4b: corr row sums, divide-free, 256 blocks x 256 threads ----
__global__ void k4b_corr() {
    int i = blockIdx.x, j = threadIdx.x;
    const double Dd = (double)DCOLS;
    const double invDm1 = 1.0 / (Dd - 1.0);
    double g = g_Gd[i * 256 + j];
    double cov = (g - Dd * g_mu[i] * g_mu[j]) * invDm1;
    double corr = cov * g_istd[i] * g_istd[j];
    double t = fmin(fabs(corr), 1.0);
    __shared__ double s1[256], s2[256];
    s1[j] = t; s2[j] = g; __syncthreads();
    for (int o = 128; o > 0; o >>= 1) {
        if (j < o) { s1[j] += s1[j + o]; s2[j] += s2[j + o]; }
        __syncthreads();
    }
    if (j == 0) { g_f1[i] = s1[0] * (1.0 / 256.0); g_rowGd[i] = s2[0]; }
}

// ---- K4c: final combine (1 block, O(B)) ----
__global__ void k4c_final() {
    __shared__ double srg[256], srmse[256], scand[256];
    __shared__ double sh_totG, sh_tmse;
    int i = threadIdx.x;
    const double Dd = (double)DCOLS;
    double rowG = g_rowGd[i];
    srg[i] = rowG;
    __syncthreads();
    if (i == 0) {
        double tg = 0.0;
        for (int j = 0; j < 256; j++) tg += srg[j];
        sh_totG = tg;
    }
    __syncthreads();
    double gii = g_Gd[i * 257];
    double rmse = (gii - (2.0 / 256.0) * rowG + sh_totG / 65536.0) / Dd;
    srmse[i] = rmse;
    __syncthreads();
    if (i == 0) {
        double tm = 0.0;
        for (int j = 0; j < 256; j++) tm += srmse[j];
        sh_tmse = tm;
    }
    __syncthreads();
    scand[i] = (1.0 - g_f1[i]) * (rmse / sh_tmse) * ((double)g_ru[i] / (double)g_tu);
    __syncthreads();
    if (i == 0) {
        double p = 0.0;   // max(max(c), 0)
        for (int j = 0; j < 256; j++) p = fmax(p, scand[j]);
        float pf = (float)p;
        g_p = pf;
        g_scale = (float)(1.0 / (1.0 - (double)pf));
    }
}

// ---- K5: streaming dropout, 4 float4 per thread, front-batched loads ----
__global__ void k5_dropout(const float* __restrict__ x, const float* __restrict__ noise,
                           float* __restrict__ out) {
    int t = threadIdx.x;
    size_t base = (size_t)blockIdx.x * 1024 + t;    // float4 units
    const float4* xp = (const float4*)x;
    const float4* np = (const float4*)noise;
    float4* op = (float4*)out;
    float p = g_p, sc = g_scale;
    float4 xv[4], nv[4];
    #pragma unroll
    for (int j = 0; j < 4; j++) xv[j] = xp[base + j * 256];
    #pragma unroll
    for (int j = 0; j < 4; j++) nv[j] = np[base + j * 256];
    #pragma unroll
    for (int j = 0; j < 4; j++) {
        float4 o;
        o.x = (nv[j].x >= p) ? xv[j].x * sc : 0.f;
        o.y = (nv[j].y >= p) ? xv[j].y * sc : 0.f;
        o.z = (nv[j].z >= p) ? xv[j].z * sc : 0.f;
        o.w = (nv[j].w >= p) ? xv[j].w * sc : 0.f;
        op[base + j * 256] = o;
    }
}

extern "C" void kernel_launch(void* const* d_in, const int* in_sizes, int n_in,
                              void* d_out, int out_size) {
    const float* x     = (const float*)d_in[0];
    const float* noise = (const float*)d_in[1];
    float* out = (float*)d_out;

    static bool attr_done = false;
    if (!attr_done) {
        cudaFuncSetAttribute(k2_gemm, cudaFuncAttributeMaxDynamicSharedMemorySize, PSTG * ABUF2);
        attr_done = true;
    }

    k1_rowstats<<<dim3(BROWS, NCHUNK1), 256>>>(x);
    k2_gemm<<<NTILE * KS2, 512, PSTG * ABUF2>>>();
    k3a_reduce<<<NTILE * 128, 128>>>();
    k3b_k4a<<<193, 256>>>();
    k4b_corr<<<256, 256>>>();
    k4c_final<<<1, 256>>>();
    size_t nvec4 = (size_t)BROWS * DCOLS / 4;            // 8388608
    k5_dropout<<<(unsigned)(nvec4 / 1024), 256>>>(x, noise, out);
}